// round 9
// baseline (speedup 1.0000x reference)
#include <cuda_runtime.h>
#include <cuda_bf16.h>

// VariableSelectionNetwork: B=32, S=512, F=32, H=64
//   A[f][g] = sum_h W_feat[f,h]*W_gate[f*H+h, g];  c = b_gate + sum b_feat.W_gate
//   gates = softmax(x @ A + c);  out = [g*x, g] @ [W_feat; b_feat]
// Prep: partial A/c over 4 h-quarters, 128 blocks.
// Main: 512 blocks x 256 threads, 32 rows/block (maximize resident warps).
//   Phase 1: 8 threads/row, 4 logits each. Phase 2: 1 row x 8 cols/thread, k=64.

#define F_DIM 32
#define H_DIM 64
#define ROWS  16384
#define MB_ROWS 32
#define MAIN_GRID (ROWS / MB_ROWS)   // 512

__device__ float g_Apart[4 * 1024];
__device__ float g_Cpart[4 * 1024];

// ---------------- f32x2 helpers ----------------
__device__ __forceinline__ unsigned long long pk2(float a, float b) {
    unsigned long long r;
    asm("mov.b64 %0, {%1, %2};" : "=l"(r) : "f"(a), "f"(b));
    return r;
}
__device__ __forceinline__ void ffma2(unsigned long long& d,
                                      unsigned long long a,
                                      unsigned long long b) {
    asm("fma.rn.f32x2 %0, %1, %2, %3;" : "=l"(d) : "l"(a), "l"(b), "l"(d));
}
__device__ __forceinline__ float2 unpk2(unsigned long long v) {
    float2 r;
    asm("mov.b64 {%0, %1}, %2;" : "=f"(r.x), "=f"(r.y) : "l"(v));
    return r;
}

// ---------------------------------------------------------------------------
// Prep: 128 blocks (f = bid>>2, h-quarter q = bid&3), 128 threads.
// ---------------------------------------------------------------------------
__global__ void __launch_bounds__(128) vsn_prep_kernel(
    const float* __restrict__ W_feat,
    const float* __restrict__ b_feat,
    const float* __restrict__ W_gate)
{
    const int f  = blockIdx.x >> 2;
    const int q  = blockIdx.x & 3;
    const int g  = threadIdx.x & 31;
    const int hh = threadIdx.x >> 5;

    float a = 0.f, c = 0.f;
#pragma unroll
    for (int kk = 0; kk < 4; kk++) {
        const int h = q * 16 + hh * 4 + kk;
        const float wg = W_gate[(f * H_DIM + h) * F_DIM + g];
        a = fmaf(W_feat[f * H_DIM + h], wg, a);
        c = fmaf(b_feat[f * H_DIM + h], wg, c);
    }

    __shared__ float rA[4][32];
    __shared__ float rC[4][32];
    rA[hh][g] = a;
    rC[hh][g] = c;
    __syncthreads();

    if (threadIdx.x < 32) {
        float as = 0.f, cs = 0.f;
#pragma unroll
        for (int r = 0; r < 4; r++) { as += rA[r][threadIdx.x]; cs += rC[r][threadIdx.x]; }
        g_Apart[q * 1024 + f * F_DIM + threadIdx.x] = as;
        g_Cpart[q * 1024 + f * F_DIM + threadIdx.x] = cs;
    }
}

// ---------------------------------------------------------------------------
// Main kernel. Static smem ~29 KB:
//   sWB [64][64] 16 KB, sX [64][32] 8 KB (k-major), sA [32][32] 4 KB.
// ---------------------------------------------------------------------------
__global__ void __launch_bounds__(256, 3) vsn_main_kernel(
    const float* __restrict__ features,
    const float* __restrict__ b_gate,
    const float* __restrict__ W_feat,
    const float* __restrict__ b_feat,
    float* __restrict__ out)
{
    __shared__ __align__(16) float sWB[2 * F_DIM * H_DIM];    // 4096
    __shared__ __align__(16) float sX [2 * F_DIM * MB_ROWS];  // 2048
    __shared__ __align__(16) float sA [F_DIM * F_DIM];        // 1024
    __shared__ __align__(16) float sc [F_DIM];
    __shared__ float sCred[8][32];

    const int tid = threadIdx.x;

    // ---- Stage params ----
#pragma unroll
    for (int i = tid; i < 1024; i += 256) {      // sWB as 1024 float4
        const int k   = i >> 4;
        const int seg = i & 15;
        const float* src = (k < F_DIM ? W_feat + k * H_DIM
                                      : b_feat + (k - F_DIM) * H_DIM) + seg * 4;
        *(float4*)(sWB + k * H_DIM + seg * 4) = *(const float4*)src;
    }
#pragma unroll
    for (int j = 0; j < 4; j++) {                // fold A partials
        const int i = tid + j * 256;
        sA[i] = g_Apart[i] + g_Apart[1024 + i] + g_Apart[2048 + i] + g_Apart[3072 + i];
    }
    {                                            // fold c partials
        const int g  = tid & 31;
        const int ch = tid >> 5;                 // 0..7
        float s = 0.f;
#pragma unroll
        for (int e = 0; e < 16; e++) {
            const int ee = ch * 16 + e;          // (q,f) flat 0..127
            s += g_Cpart[(ee >> 5) * 1024 + (ee & 31) * F_DIM + g];
        }
        sCred[ch][g] = s;
    }
    __syncthreads();
    if (tid < 32) {
        float cv = b_gate[tid];
#pragma unroll
        for (int r = 0; r < 8; r++) cv += sCred[r][tid];
        sc[tid] = cv;
    }
    __syncthreads();

    // ---- Phase 1: gates (8 threads/row, 4 logits each) ----
    const int rowL = tid >> 3;                   // 0..31
    const int q    = tid & 7;                    // 0..7
    const int row  = blockIdx.x * MB_ROWS + rowL;

    float x[F_DIM];
    {
        const float4* xr = (const float4*)(features + row * F_DIM);
#pragma unroll
        for (int i = 0; i < 8; i++) {
            float4 v = xr[i];
            x[4*i+0] = v.x; x[4*i+1] = v.y; x[4*i+2] = v.z; x[4*i+3] = v.w;
        }
    }

    // logits l[4] = x @ A[:, q*4 .. q*4+4) + c
    unsigned long long l2[2];
    {
        const ulonglong2 cv = *(const ulonglong2*)(sc + q * 4);
        l2[0] = cv.x; l2[1] = cv.y;
    }
#pragma unroll
    for (int f = 0; f < F_DIM; f++) {
        const unsigned long long xp = pk2(x[f], x[f]);
        const ulonglong2 av = *(const ulonglong2*)(sA + f * F_DIM + q * 4);
        ffma2(l2[0], xp, av.x);
        ffma2(l2[1], xp, av.y);
    }
    float le[4];
    {
        float2 v0 = unpk2(l2[0]), v1 = unpk2(l2[1]);
        le[0] = v0.x; le[1] = v0.y; le[2] = v1.x; le[3] = v1.y;
    }

    // softmax across 8 threads (octet)
    float m = fmaxf(fmaxf(le[0], le[1]), fmaxf(le[2], le[3]));
    m = fmaxf(m, __shfl_xor_sync(0xffffffffu, m, 1));
    m = fmaxf(m, __shfl_xor_sync(0xffffffffu, m, 2));
    m = fmaxf(m, __shfl_xor_sync(0xffffffffu, m, 4));
    float s = 0.f;
#pragma unroll
    for (int j = 0; j < 4; j++) { le[j] = __expf(le[j] - m); s += le[j]; }
    s += __shfl_xor_sync(0xffffffffu, s, 1);
    s += __shfl_xor_sync(0xffffffffu, s, 2);
    s += __shfl_xor_sync(0xffffffffu, s, 4);
    const float inv = 1.f / s;

    // Write X' (k-major): sX[f][rowL] = g*x[f]; sX[32+f][rowL] = g
    const int fb = q * 4;
#pragma unroll
    for (int j = 0; j < 4; j++) {
        const float gj = le[j] * inv;
        sX[(fb + j) * MB_ROWS + rowL]         = gj * x[fb + j];
        sX[(F_DIM + fb + j) * MB_ROWS + rowL] = gj;
    }
    __syncthreads();

    // ---- Phase 2: out = X' @ W', 1 row x 8 cols per thread, k=64 ----
    const int r2 = tid >> 3;        // 0..31: row
    const int cg = tid & 7;         // 0..7: col group
    const int c0 = cg * 8;

    unsigned long long acc[4];
    acc[0] = acc[1] = acc[2] = acc[3] = 0ull;

#pragma unroll 16
    for (int k = 0; k < 2 * F_DIM; k++) {
        const float xk = sX[k * MB_ROWS + r2];
        const unsigned long long xp = pk2(xk, xk);
        const ulonglong2* wp = (const ulonglong2*)(sWB + k * H_DIM + c0);
        const ulonglong2 w0 = wp[0], w1 = wp[1];
        ffma2(acc[0], xp, w0.x);
        ffma2(acc[1], xp, w0.y);
        ffma2(acc[2], xp, w1.x);
        ffma2(acc[3], xp, w1.y);
    }

    // Store 1 row x 8 cols
    {
        const float2 v0 = unpk2(acc[0]);
        const float2 v1 = unpk2(acc[1]);
        const float2 v2 = unpk2(acc[2]);
        const float2 v3 = unpk2(acc[3]);
        float* dst = out + (blockIdx.x * MB_ROWS + r2) * H_DIM + c0;
        *(float4*)(dst)     = make_float4(v0.x, v0.y, v1.x, v1.y);
        *(float4*)(dst + 4) = make_float4(v2.x, v2.y, v3.x, v3.y);
    }
}

extern "C" void kernel_launch(void* const* d_in, const int* in_sizes, int n_in,
                              void* d_out, int out_size)
{
    const float* features = (const float*)d_in[0];   // [32,512,32]
    const float* W_feat   = (const float*)d_in[1];   // [32,64]
    const float* b_feat   = (const float*)d_in[2];   // [32,64]
    const float* W_gate   = (const float*)d_in[3];   // [2048,32]
    const float* b_gate   = (const float*)d_in[4];   // [32]
    float* out = (float*)d_out;                      // [32,512,64]

    vsn_prep_kernel<<<128, 128>>>(W_feat, b_feat, W_gate);
    vsn_main_kernel<<<MAIN_GRID, 256>>>(features, b_gate, W_feat, b_feat, out);
}

// round 10
// speedup vs baseline: 2.0618x; 2.0618x over previous
#include <cuda_runtime.h>
#include <cuda_bf16.h>

// VariableSelectionNetwork: B=32, S=512, F=32, H=64
//   A[f][g] = sum_h W_feat[f,h]*W_gate[f*H+h, g];  c = b_gate + sum b_feat.W_gate
//   gates = softmax(x @ A + c);  out = [g*x, g] @ [W_feat; b_feat]
// Prep: partial A/c over 4 h-quarters, 128 blocks.
// Main: 256 blocks x 256 threads, 64 rows/block.
//   Phase 2: tile 8 rows x 4 cols, split-k-2, row-pair f32x2 accumulation
//   (x pairs straight from LDS.128, only w duplicated -> 4 movs / 16 ffma2).

#define F_DIM 32
#define H_DIM 64
#define ROWS  16384
#define MB_ROWS 64
#define MAIN_GRID (ROWS / MB_ROWS)   // 256

typedef unsigned long long ull;

__device__ float g_Apart[4 * 1024];
__device__ float g_Cpart[4 * 1024];

// ---------------- f32x2 helpers ----------------
__device__ __forceinline__ ull pk2(float a, float b) {
    ull r;
    asm("mov.b64 %0, {%1, %2};" : "=l"(r) : "f"(a), "f"(b));
    return r;
}
__device__ __forceinline__ void ffma2(ull& d, ull a, ull b) {
    asm("fma.rn.f32x2 %0, %1, %2, %3;" : "=l"(d) : "l"(a), "l"(b), "l"(d));
}
__device__ __forceinline__ void fadd2(ull& d, ull a) {
    asm("add.rn.f32x2 %0, %1, %2;" : "=l"(d) : "l"(d), "l"(a));
}
__device__ __forceinline__ float2 unpk2(ull v) {
    float2 r;
    asm("mov.b64 {%0, %1}, %2;" : "=f"(r.x), "=f"(r.y) : "l"(v));
    return r;
}

// ---------------------------------------------------------------------------
// Prep: 128 blocks (f = bid>>2, h-quarter q = bid&3), 128 threads.
// ---------------------------------------------------------------------------
__global__ void __launch_bounds__(128) vsn_prep_kernel(
    const float* __restrict__ W_feat,
    const float* __restrict__ b_feat,
    const float* __restrict__ W_gate)
{
    const int f  = blockIdx.x >> 2;
    const int q  = blockIdx.x & 3;
    const int g  = threadIdx.x & 31;
    const int hh = threadIdx.x >> 5;

    float a = 0.f, c = 0.f;
#pragma unroll
    for (int kk = 0; kk < 4; kk++) {
        const int h = q * 16 + hh * 4 + kk;
        const float wg = W_gate[(f * H_DIM + h) * F_DIM + g];
        a = fmaf(W_feat[f * H_DIM + h], wg, a);
        c = fmaf(b_feat[f * H_DIM + h], wg, c);
    }

    __shared__ float rA[4][32];
    __shared__ float rC[4][32];
    rA[hh][g] = a;
    rC[hh][g] = c;
    __syncthreads();

    if (threadIdx.x < 32) {
        float as = 0.f, cs = 0.f;
#pragma unroll
        for (int r = 0; r < 4; r++) { as += rA[r][threadIdx.x]; cs += rC[r][threadIdx.x]; }
        g_Apart[q * 1024 + f * F_DIM + threadIdx.x] = as;
        g_Cpart[q * 1024 + f * F_DIM + threadIdx.x] = cs;
    }
}

// ---------------------------------------------------------------------------
// Main kernel. Static smem ~37 KB:
//   sWB [64][64] 16 KB, sX [64][64] 16 KB (k-major; reused as split-k buffer),
//   sA [32][32] 4 KB.
// ---------------------------------------------------------------------------
__global__ void __launch_bounds__(256) vsn_main_kernel(
    const float* __restrict__ features,
    const float* __restrict__ b_gate,
    const float* __restrict__ W_feat,
    const float* __restrict__ b_feat,
    float* __restrict__ out)
{
    __shared__ __align__(16) float sWB[2 * F_DIM * H_DIM];    // 4096 floats
    __shared__ __align__(16) float sX [2 * F_DIM * MB_ROWS];  // 4096 floats
    __shared__ __align__(16) float sA [F_DIM * F_DIM];        // 1024 floats
    __shared__ __align__(16) float sc [F_DIM];
    __shared__ float sCred[8][32];

    const int tid = threadIdx.x;

    // ---- Stage params ----
#pragma unroll
    for (int i = tid; i < 1024; i += 256) {      // sWB as 1024 float4
        const int k   = i >> 4;
        const int seg = i & 15;
        const float* src = (k < F_DIM ? W_feat + k * H_DIM
                                      : b_feat + (k - F_DIM) * H_DIM) + seg * 4;
        *(float4*)(sWB + k * H_DIM + seg * 4) = *(const float4*)src;
    }
#pragma unroll
    for (int j = 0; j < 4; j++) {                // fold A partials
        const int i = tid + j * 256;
        sA[i] = g_Apart[i] + g_Apart[1024 + i] + g_Apart[2048 + i] + g_Apart[3072 + i];
    }
    {                                            // fold c partials
        const int g  = tid & 31;
        const int ch = tid >> 5;                 // 0..7
        float s = 0.f;
#pragma unroll
        for (int e = 0; e < 16; e++) {
            const int ee = ch * 16 + e;          // (q,f) flat 0..127
            s += g_Cpart[(ee >> 5) * 1024 + (ee & 31) * F_DIM + g];
        }
        sCred[ch][g] = s;
    }
    __syncthreads();
    if (tid < 32) {
        float cv = b_gate[tid];
#pragma unroll
        for (int r = 0; r < 8; r++) cv += sCred[r][tid];
        sc[tid] = cv;
    }
    __syncthreads();

    // ---- Phase 1: gates (quad: 4 threads/row, 8 logits each) ----
    const int rowL = tid >> 2;                   // 0..63
    const int q    = tid & 3;
    const int row  = blockIdx.x * MB_ROWS + rowL;

    float x[F_DIM];
    {
        const float4* xr = (const float4*)(features + row * F_DIM);
#pragma unroll
        for (int i = 0; i < 8; i++) {
            float4 v = xr[i];
            x[4*i+0] = v.x; x[4*i+1] = v.y; x[4*i+2] = v.z; x[4*i+3] = v.w;
        }
    }

    ull l2[4];
    {
        const ulonglong2* cp = (const ulonglong2*)(sc + q * 8);
        ulonglong2 ca = cp[0], cb = cp[1];
        l2[0] = ca.x; l2[1] = ca.y; l2[2] = cb.x; l2[3] = cb.y;
    }
#pragma unroll
    for (int f = 0; f < F_DIM; f++) {
        const ull xp = pk2(x[f], x[f]);
        const ulonglong2* ap = (const ulonglong2*)(sA + f * F_DIM + q * 8);
        ulonglong2 a0 = ap[0], a1 = ap[1];
        ffma2(l2[0], xp, a0.x); ffma2(l2[1], xp, a0.y);
        ffma2(l2[2], xp, a1.x); ffma2(l2[3], xp, a1.y);
    }
    float le[8];
#pragma unroll
    for (int i = 0; i < 4; i++) {
        float2 v = unpk2(l2[i]);
        le[2*i] = v.x; le[2*i+1] = v.y;
    }

    // softmax across quad
    float m = le[0];
#pragma unroll
    for (int j = 1; j < 8; j++) m = fmaxf(m, le[j]);
    m = fmaxf(m, __shfl_xor_sync(0xffffffffu, m, 1));
    m = fmaxf(m, __shfl_xor_sync(0xffffffffu, m, 2));
    float s = 0.f;
#pragma unroll
    for (int j = 0; j < 8; j++) { le[j] = __expf(le[j] - m); s += le[j]; }
    s += __shfl_xor_sync(0xffffffffu, s, 1);
    s += __shfl_xor_sync(0xffffffffu, s, 2);
    const float inv = 1.f / s;

    // Write X' (k-major): sX[f][rowL] = g*x[f]; sX[32+f][rowL] = g
    const int fb = q * 8;
#pragma unroll
    for (int j = 0; j < 8; j++) {
        const float gj = le[j] * inv;
        sX[(fb + j) * MB_ROWS + rowL]         = gj * x[fb + j];
        sX[(F_DIM + fb + j) * MB_ROWS + rowL] = gj;
    }
    __syncthreads();

    // ---- Phase 2: out = X' @ W', tile 8 rows x 4 cols, split-k-2 ----
    const int slice = tid >> 7;     // 0/1: k-half
    const int tt    = tid & 127;
    const int rg    = tt >> 4;      // 0..7  -> rows rg*8
    const int cg    = tt & 15;      // 0..15 -> cols cg*4
    const int r0    = rg * 8;
    const int c0    = cg * 4;
    const int kbase = slice * F_DIM;

    ull acc[4][4];                  // [col][row-pair]
#pragma unroll
    for (int c2 = 0; c2 < 4; c2++)
#pragma unroll
        for (int rp = 0; rp < 4; rp++) acc[c2][rp] = 0ull;

#pragma unroll 8
    for (int kk = 0; kk < F_DIM; kk++) {
        const int k = kbase + kk;
        // x row-pairs straight from LDS.128 (adjacent reg pairs, no movs)
        const ulonglong2 xa = *(const ulonglong2*)(sX + k * MB_ROWS + r0);
        const ulonglong2 xb = *(const ulonglong2*)(sX + k * MB_ROWS + r0 + 4);
        const float4 wv = *(const float4*)(sWB + k * H_DIM + c0);
        const ull w0 = pk2(wv.x, wv.x);
        const ull w1 = pk2(wv.y, wv.y);
        const ull w2 = pk2(wv.z, wv.z);
        const ull w3 = pk2(wv.w, wv.w);

        ffma2(acc[0][0], xa.x, w0); ffma2(acc[0][1], xa.y, w0);
        ffma2(acc[0][2], xb.x, w0); ffma2(acc[0][3], xb.y, w0);
        ffma2(acc[1][0], xa.x, w1); ffma2(acc[1][1], xa.y, w1);
        ffma2(acc[1][2], xb.x, w1); ffma2(acc[1][3], xb.y, w1);
        ffma2(acc[2][0], xa.x, w2); ffma2(acc[2][1], xa.y, w2);
        ffma2(acc[2][2], xb.x, w2); ffma2(acc[2][3], xb.y, w2);
        ffma2(acc[3][0], xa.x, w3); ffma2(acc[3][1], xa.y, w3);
        ffma2(acc[3][2], xb.x, w3); ffma2(acc[3][3], xb.y, w3);
    }
    __syncthreads();   // all sX reads done; reuse as split-k buffer (2048 ull)

    ull* red = (ull*)sX;
    if (slice == 1) {
#pragma unroll
        for (int c2 = 0; c2 < 4; c2++)
#pragma unroll
            for (int rp = 0; rp < 4; rp++)
                red[(c2 * 4 + rp) * 128 + tt] = acc[c2][rp];
    }
    __syncthreads();

    if (slice == 0) {
#pragma unroll
        for (int c2 = 0; c2 < 4; c2++)
#pragma unroll
            for (int rp = 0; rp < 4; rp++)
                fadd2(acc[c2][rp], red[(c2 * 4 + rp) * 128 + tt]);

        // unpack: acc[c][rp] = {out[r0+2rp][c0+c], out[r0+2rp+1][c0+c]}
        float o[8][4];
#pragma unroll
        for (int c2 = 0; c2 < 4; c2++)
#pragma unroll
            for (int rp = 0; rp < 4; rp++) {
                const float2 v = unpk2(acc[c2][rp]);
                o[rp * 2 + 0][c2] = v.x;
                o[rp * 2 + 1][c2] = v.y;
            }
        const int rowbase = blockIdx.x * MB_ROWS + r0;
#pragma unroll
        for (int r = 0; r < 8; r++) {
            *(float4*)(out + (rowbase + r) * H_DIM + c0) =
                make_float4(o[r][0], o[r][1], o[r][2], o[r][3]);
        }
    }
}

extern "C" void kernel_launch(void* const* d_in, const int* in_sizes, int n_in,
                              void* d_out, int out_size)
{
    const float* features = (const float*)d_in[0];   // [32,512,32]
    const float* W_feat   = (const float*)d_in[1];   // [32,64]
    const float* b_feat   = (const float*)d_in[2];   // [32,64]
    const float* W_gate   = (const float*)d_in[3];   // [2048,32]
    const float* b_gate   = (const float*)d_in[4];   // [32]
    float* out = (float*)d_out;                      // [32,512,64]

    vsn_prep_kernel<<<128, 128>>>(W_feat, b_feat, W_gate);
    vsn_main_kernel<<<MAIN_GRID, 256>>>(features, b_gate, W_feat, b_feat, out);
}